// round 5
// baseline (speedup 1.0000x reference)
#include <cuda_runtime.h>
#include <cuda_bf16.h>
#include <mma.h>

using namespace nvcuda;

#define NUSER 50000
#define NITEM 100000
#define NNODE 150000
#define NPAD  150016          // multiple of 512 (293*512)
#define NB_SCAN 293
#define NNZ   2000000
#define D     80              // 64 light + 16 mm, fused
#define BATCH 1024
#define NTAIL0 99968          // 781*128

// ---------------- static device scratch (no cudaMalloc allowed) ----------------
__device__ float g_X0[(size_t)NPAD * D];
__device__ float g_X1[(size_t)NPAD * D];
__device__ float g_X2[(size_t)NPAD * D];
__device__ float g_X3[(size_t)NPAD * D];
__device__ int   g_cnt[NPAD];
__device__ int   g_rowptr[NPAD];
__device__ int   g_cursor[NPAD];
__device__ int   g_bsum[512];
__device__ int   g_boff[512];
__device__ int   g_ci[NNZ];
__device__ float g_cv[NNZ];
__device__ __nv_bfloat16 g_UA[BATCH * D];            // augmented users (bf16)
__device__ __nv_bfloat16 g_IA[(size_t)NITEM * D];    // augmented items (bf16)

__device__ __forceinline__ float* pick_buf(int s) {
    return (s == 0) ? g_X0 : (s == 1) ? g_X1 : (s == 2) ? g_X2 : g_X3;
}

__device__ __forceinline__ float sigmoidf(float x) {
    return 1.0f / (1.0f + __expf(-x));
}

// ---------------- CSR construction ----------------
__global__ void k_zero_cnt() {
    int i = blockIdx.x * blockDim.x + threadIdx.x;
    if (i < NPAD) g_cnt[i] = 0;
}

__global__ void k_count(const int* __restrict__ rows) {
    int i = blockIdx.x * blockDim.x + threadIdx.x;
    if (i < NNZ) atomicAdd(&g_cnt[rows[i]], 1);
}

// per-block exclusive scan (512 wide) + block totals
__global__ void k_scan_block() {
    __shared__ int s[512];
    int t = threadIdx.x;
    int i = blockIdx.x * 512 + t;
    int v = g_cnt[i];
    s[t] = v;
    __syncthreads();
    #pragma unroll
    for (int off = 1; off < 512; off <<= 1) {
        int x = (t >= off) ? s[t - off] : 0;
        __syncthreads();
        s[t] += x;
        __syncthreads();
    }
    g_rowptr[i] = s[t] - v;           // block-local exclusive
    if (t == 511) g_bsum[blockIdx.x] = s[511];
}

__global__ void k_scan_bsum() {
    __shared__ int s[512];
    int t = threadIdx.x;
    int v = (t < NB_SCAN) ? g_bsum[t] : 0;
    s[t] = v;
    __syncthreads();
    #pragma unroll
    for (int off = 1; off < 512; off <<= 1) {
        int x = (t >= off) ? s[t - off] : 0;
        __syncthreads();
        s[t] += x;
        __syncthreads();
    }
    g_boff[t] = s[t] - v;             // exclusive
}

__global__ void k_scan_add() {
    int t = threadIdx.x;
    int i = blockIdx.x * 512 + t;
    int r = g_rowptr[i] + g_boff[blockIdx.x];
    g_rowptr[i] = r;
    g_cursor[i] = r;
}

__global__ void k_fill(const int* __restrict__ rows, const int* __restrict__ cols,
                       const float* __restrict__ vals) {
    int i = blockIdx.x * blockDim.x + threadIdx.x;
    if (i >= NNZ) return;
    int r = rows[i];
    int p = atomicAdd(&g_cursor[r], 1);
    g_ci[p] = cols[i];
    g_cv[p] = vals[i];
}

// ---------------- init X0 = concat(emb, mm_emb) ----------------
__global__ void k_init(const float* __restrict__ eu, const float* __restrict__ ei,
                       const float* __restrict__ mu, const float* __restrict__ mi) {
    int i = blockIdx.x * blockDim.x + threadIdx.x;
    if (i >= NNODE * D) return;
    int n = i / D, d = i % D;
    float v;
    if (n < NUSER) {
        v = (d < 64) ? eu[n * 64 + d] : mu[n * 16 + (d - 64)];
    } else {
        int m = n - NUSER;
        v = (d < 64) ? ei[m * 64 + d] : mi[m * 16 + (d - 64)];
    }
    g_X0[(size_t)n * D + d] = v;
}

// ---------------- gather SpMM: one row per warp ----------------
__global__ void k_spmm(int layer) {
    const float* __restrict__ Xin = pick_buf(layer);
    float* __restrict__ Xout = pick_buf(layer + 1);
    int row = blockIdx.x * (blockDim.x >> 5) + (threadIdx.x >> 5);
    if (row >= NPAD) return;
    int lane = threadIdx.x & 31;
    int start = g_rowptr[row];
    int deg = g_cnt[row];
    float a0 = 0.f, a1 = 0.f, a2 = 0.f;
    for (int e = 0; e < deg; e++) {
        int c = __ldg(&g_ci[start + e]);
        float v = __ldg(&g_cv[start + e]);
        const float* xr = Xin + (size_t)c * D;
        a0 += v * __ldg(xr + lane);
        a1 += v * __ldg(xr + 32 + lane);
        if (lane < 16) a2 += v * __ldg(xr + 64 + lane);
    }
    float* o = Xout + (size_t)row * D;
    o[lane] = a0;
    o[32 + lane] = a1;
    if (lane < 16) o[64 + lane] = a2;
}

// ---------------- augmented user / item builders (bf16, /4 folded in) ----------------
__global__ void k_uaug(const int* __restrict__ users, const float* __restrict__ bias_user) {
    int i = blockIdx.x * blockDim.x + threadIdx.x;
    if (i >= BATCH * D) return;
    int b = i / D, d = i % D;
    int u = users[b];
    float v;
    if (d < 64) {
        size_t o = (size_t)u * D;
        float sl = g_X0[o + d] + g_X1[o + d] + g_X2[o + d] + g_X3[o + d];
        size_t om = o + 64 + (d >> 2);
        float sm = g_X0[om] + g_X1[om] + g_X2[om] + g_X3[om];
        v = 0.25f * (sl + sm);
    } else if (d == 64) v = bias_user[u];
    else if (d == 65) v = 1.0f;
    else v = 0.0f;
    g_UA[i] = __float2bfloat16(v);
}

__global__ void k_iaug(const float* __restrict__ bias_item) {
    int i = blockIdx.x * blockDim.x + threadIdx.x;
    if (i >= NITEM * D) return;
    int it = i / D, d = i % D;
    size_t o = (size_t)(NUSER + it) * D;
    float v;
    if (d < 64) {
        float sl = g_X0[o + d] + g_X1[o + d] + g_X2[o + d] + g_X3[o + d];
        size_t om = o + 64 + (d >> 2);
        float sm = g_X0[om] + g_X1[om] + g_X2[om] + g_X3[om];
        v = 0.25f * (sl + sm);
    } else if (d == 64) v = 1.0f;
    else if (d == 65) v = bias_item[it];
    else v = 0.0f;
    g_IA[i] = __float2bfloat16(v);
}

// ---------------- GEMM: [1024,80]bf16 x [N,80]bf16^T -> sigmoid -> f32 ----------------
// block tile 128x128, 8 warps each 32x64, K=80 (5 steps of 16)
__global__ void __launch_bounds__(256) k_gemm(float* __restrict__ out) {
    __shared__ alignas(16) __nv_bfloat16 As[128][88];
    __shared__ alignas(16) __nv_bfloat16 Bs[128][88];
    int m0 = blockIdx.y * 128;
    int n0 = blockIdx.x * 128;
    int t = threadIdx.x;

    const uint4* ua = (const uint4*)g_UA;   // 10 uint4 per row (80 bf16 = 160B)
    const uint4* ia = (const uint4*)g_IA;
    #pragma unroll
    for (int idx = t; idx < 1280; idx += 256) {
        int r = idx / 10, c = idx % 10;
        *(uint4*)(&As[r][c * 8]) = ua[(size_t)(m0 + r) * 10 + c];
    }
    #pragma unroll
    for (int idx = t; idx < 1280; idx += 256) {
        int r = idx / 10, c = idx % 10;
        *(uint4*)(&Bs[r][c * 8]) = ia[(size_t)(n0 + r) * 10 + c];
    }
    __syncthreads();

    int w = t >> 5;
    int wm = (w >> 1) * 32;   // 0,32,64,96
    int wn = (w & 1) * 64;    // 0,64

    wmma::fragment<wmma::accumulator, 16, 16, 16, float> acc[2][4];
    #pragma unroll
    for (int i = 0; i < 2; i++)
        #pragma unroll
        for (int j = 0; j < 4; j++)
            wmma::fill_fragment(acc[i][j], 0.0f);

    #pragma unroll
    for (int k = 0; k < 80; k += 16) {
        wmma::fragment<wmma::matrix_a, 16, 16, 16, __nv_bfloat16, wmma::row_major> a[2];
        wmma::fragment<wmma::matrix_b, 16, 16, 16, __nv_bfloat16, wmma::col_major> b[4];
        #pragma unroll
        for (int i = 0; i < 2; i++)
            wmma::load_matrix_sync(a[i], &As[wm + 16 * i][0] + k, 88);
        #pragma unroll
        for (int j = 0; j < 4; j++)
            wmma::load_matrix_sync(b[j], &Bs[wn + 16 * j][0] + k, 88);
        #pragma unroll
        for (int i = 0; i < 2; i++)
            #pragma unroll
            for (int j = 0; j < 4; j++)
                wmma::mma_sync(acc[i][j], a[i], b[j], acc[i][j]);
    }

    #pragma unroll
    for (int i = 0; i < 2; i++) {
        #pragma unroll
        for (int j = 0; j < 4; j++) {
            #pragma unroll
            for (int e = 0; e < acc[i][j].num_elements; e++)
                acc[i][j].x[e] = sigmoidf(acc[i][j].x[e]);
            wmma::store_matrix_sync(
                out + (size_t)(m0 + wm + 16 * i) * NITEM + (n0 + wn + 16 * j),
                acc[i][j], NITEM, wmma::mem_row_major);
        }
    }
}

// ---------------- tail: columns [99968, 100000) ----------------
__global__ void k_tail(float* __restrict__ out) {
    int i = blockIdx.x * blockDim.x + threadIdx.x;
    if (i >= BATCH * 32) return;
    int b = i >> 5, j = i & 31;
    int n = NTAIL0 + j;
    const __nv_bfloat16* u = g_UA + (size_t)b * D;
    const __nv_bfloat16* v = g_IA + (size_t)n * D;
    float s = 0.f;
    #pragma unroll
    for (int k = 0; k < D; k++)
        s += __bfloat162float(u[k]) * __bfloat162float(v[k]);
    out[(size_t)b * NITEM + n] = sigmoidf(s);
}

// ---------------- launcher ----------------
extern "C" void kernel_launch(void* const* d_in, const int* in_sizes, int n_in,
                              void* d_out, int out_size) {
    const float* emb_user  = (const float*)d_in[0];
    const float* emb_item  = (const float*)d_in[1];
    const float* bias_user = (const float*)d_in[2];
    const float* bias_item = (const float*)d_in[3];
    const float* mm_user   = (const float*)d_in[4];
    const float* mm_item   = (const float*)d_in[5];
    const float* vals      = (const float*)d_in[6];
    const int*   users     = (const int*)d_in[7];
    const int*   rows      = (const int*)d_in[8];
    const int*   cols      = (const int*)d_in[9];
    float* out = (float*)d_out;

    // CSR build
    k_zero_cnt<<<(NPAD + 255) / 256, 256>>>();
    k_count<<<(NNZ + 255) / 256, 256>>>(rows);
    k_scan_block<<<NB_SCAN, 512>>>();
    k_scan_bsum<<<1, 512>>>();
    k_scan_add<<<NB_SCAN, 512>>>();
    k_fill<<<(NNZ + 255) / 256, 256>>>(rows, cols, vals);

    // X0
    k_init<<<(NNODE * D + 255) / 256, 256>>>(emb_user, emb_item, mm_user, mm_item);

    // 3 propagation layers (gather, no atomics)
    for (int L = 0; L < 3; L++)
        k_spmm<<<NPAD / 8, 256>>>(L);

    // augmented embeddings
    k_uaug<<<(BATCH * D + 255) / 256, 256>>>(users, bias_user);
    k_iaug<<<(NITEM * D + 255) / 256, 256>>>(bias_item);

    // main GEMM + tail
    dim3 grid(NTAIL0 / 128, BATCH / 128);
    k_gemm<<<grid, 256>>>(out);
    k_tail<<<(BATCH * 32 + 255) / 256, 256>>>(out);
}